// round 17
// baseline (speedup 1.0000x reference)
#include <cuda_runtime.h>
#include <cuda_fp16.h>
#include <cstdint>

// ---------------------------------------------------------------------------
// Problem constants
// ---------------------------------------------------------------------------
#define BATCH      2048
#define MSEQ       64
#define STATE_DIM  32
#define CONTROL_DIM 8
#define EMBED_DIM  96
#define LATENT_DIM 128
#define HIDDEN     512
#define ROWS_XNEXT (BATCH * MSEQ)            // 131072
#define ROWS_TOTAL (BATCH + ROWS_XNEXT)      // 133120
#define MTILES     (ROWS_TOTAL / 128)        // 1040

// ---------------------------------------------------------------------------
// Scratch (__device__ globals; no allocs allowed)
// ---------------------------------------------------------------------------
__device__ __half g_Hahi[(size_t)ROWS_TOTAL * HIDDEN];   // H1 / H3 (single fp16)
__device__ __half g_Hbhi[(size_t)ROWS_TOTAL * HIDDEN];   // H2 (single fp16)
__device__ float  g_Exk[(size_t)BATCH * EMBED_DIM];      // encoder(x_k) only
__device__ __half g_W1thi[512 * 32];                     // [N][K]
__device__ __half g_W2thi[512 * 512];
__device__ __half g_W3thi[512 * 512];
__device__ __half g_Wothi[128 * 512];                    // padded N 96->128

// ---------------------------------------------------------------------------
// Helpers
// ---------------------------------------------------------------------------
__device__ __forceinline__ uint32_t smem_u32(const void* p) {
    uint32_t a;
    asm("{ .reg .u64 t; cvta.to.shared.u64 t, %1; cvt.u32.u64 %0, t; }"
        : "=r"(a) : "l"(p));
    return a;
}

#define CP16(dst, src) \
    asm volatile("cp.async.cg.shared.global [%0], [%1], 16;" \
                 :: "r"(dst), "l"(src))
#define CP_COMMIT() asm volatile("cp.async.commit_group;")
#define CP_WAIT(n)  asm volatile("cp.async.wait_group %0;" :: "n"(n))

__device__ __forceinline__ void ldsm4(uint32_t* d, uint32_t addr) {
    asm volatile("ldmatrix.sync.aligned.m8n8.x4.shared.b16 {%0,%1,%2,%3}, [%4];"
                 : "=r"(d[0]), "=r"(d[1]), "=r"(d[2]), "=r"(d[3]) : "r"(addr));
}
__device__ __forceinline__ void mma16816(float* c, const uint32_t* a,
                                         uint32_t b0, uint32_t b1) {
    asm volatile(
        "mma.sync.aligned.m16n8k16.row.col.f32.f16.f16.f32 "
        "{%0,%1,%2,%3}, {%4,%5,%6,%7}, {%8,%9}, {%0,%1,%2,%3};"
        : "+f"(c[0]), "+f"(c[1]), "+f"(c[2]), "+f"(c[3])
        : "r"(a[0]), "r"(a[1]), "r"(a[2]), "r"(a[3]), "r"(b0), "r"(b1));
}

__device__ __forceinline__ void split_h(float v, __half& h, __half& l) {
    h = __float2half(v);
    l = __float2half(v - __half2float(h));
}
__device__ __forceinline__ uint32_t pack_h2(float a, float b) {
    __half2 h = __floats2half2_rn(a, b);
    return *reinterpret_cast<uint32_t*>(&h);
}

#define TILE_B  10240          // 128 rows * 80 bytes

// ---------------------------------------------------------------------------
// gemm_l1: fused X-split + 2-pass K=32 GEMM (layer 1).
// Stages fp32 x rows via cp.async, converts to hi/lo fp16 smem tiles
// ([Ah][Al][Bh] at the same offsets the proven template uses), then runs the
// identical 2-pass 64x32-warp-tile compute and OUTM1 epilogue.
// smem: 3*TILE_B + 16KB staging = 47104 B -> 2 blocks/SM.
// ---------------------------------------------------------------------------
#define L1_SMEM (3 * TILE_B + 16384)

__global__ __launch_bounds__(256, 2)
void gemm_l1(const float* __restrict__ x_k, const float* __restrict__ x_next,
             const __half* __restrict__ Bhi,
             const float* __restrict__ bias,
             __half* __restrict__ Chi)
{
    extern __shared__ __align__(128) uint8_t dsm[];
    const uint32_t sbase = smem_u32(dsm);
    const uint32_t AH = sbase, AL = sbase + TILE_B, BH = sbase + 2 * TILE_B;
    const uint32_t STAGE = sbase + 3 * TILE_B;

    const int tid  = threadIdx.x;
    const int wid  = tid >> 5;
    const int lane = tid & 31;
    const int row0 = blockIdx.y * 128;
    const int n0   = blockIdx.x * 128;

    const float* xsrc = (row0 < BATCH) ? (x_k + (size_t)row0 * 32)
                                       : (x_next + (size_t)(row0 - BATCH) * 32);

    // stage fp32 x: 128 rows x 128B = 1024 chunks (4/thread)
    #pragma unroll
    for (int t = 0; t < 4; t++) {
        int q = tid + t * 256;
        int r = q >> 3, c = q & 7;
        CP16(STAGE + (uint32_t)r * 128 + c * 16, xsrc + (size_t)r * 32 + c * 4);
    }
    // B tile: 128 rows x 32 fp16 (64B rows) = 512 chunks (2/thread)
    #pragma unroll
    for (int t = 0; t < 2; t++) {
        int q = tid + t * 256;
        int r = q >> 2, c = q & 3;
        CP16(BH + (uint32_t)r * 80 + c * 16, Bhi + (size_t)(n0 + r) * 32 + c * 8);
    }
    CP_COMMIT();
    CP_WAIT(0);
    __syncthreads();

    // convert: thread handles row tid>>1, k-halves (tid&1)*16..+15
    {
        const int r = tid >> 1, half = tid & 1;
        #pragma unroll
        for (int j = 0; j < 8; j++) {
            float2 f;
            asm volatile("ld.shared.v2.f32 {%0, %1}, [%2];"
                         : "=f"(f.x), "=f"(f.y)
                         : "r"(STAGE + (uint32_t)r * 128 + half * 64 + j * 8));
            __half h0, l0, h1, l1;
            split_h(f.x, h0, l0);
            split_h(f.y, h1, l1);
            uint32_t ph = (uint32_t)__half_as_ushort(h0)
                        | ((uint32_t)__half_as_ushort(h1) << 16);
            uint32_t pl = (uint32_t)__half_as_ushort(l0)
                        | ((uint32_t)__half_as_ushort(l1) << 16);
            uint32_t so = (uint32_t)r * 80 + half * 32 + j * 4;
            asm volatile("st.shared.b32 [%0], %1;" :: "r"(AH + so), "r"(ph));
            asm volatile("st.shared.b32 [%0], %1;" :: "r"(AL + so), "r"(pl));
        }
    }
    __syncthreads();

    const int m_base = (wid >> 2) * 64;
    const int n_base = (wid & 3) * 32;
    const uint32_t aoff = (uint32_t)(m_base + (lane & 15)) * 80 + ((lane >> 4) << 4);
    const uint32_t boff = (uint32_t)(n_base + (lane & 15)) * 80 + ((lane >> 4) << 4);

    float acc[4][4][4];
    #pragma unroll
    for (int f = 0; f < 4; f++)
        #pragma unroll
        for (int g = 0; g < 4; g++)
            #pragma unroll
            for (int e = 0; e < 4; e++)
                acc[f][g][e] = 0.f;

    // 2-pass compute, K=32 (2 ks), pass-major (identical order to template)
    #pragma unroll
    for (int ks = 0; ks < 2; ks++) {
        uint32_t ah[4][4], bh[2][4];
        #pragma unroll
        for (int f = 0; f < 4; f++)
            ldsm4(ah[f], AH + aoff + f * (16 * 80) + ks * 32);
        #pragma unroll
        for (int p = 0; p < 2; p++)
            ldsm4(bh[p], BH + boff + p * (16 * 80) + ks * 32);
        #pragma unroll
        for (int f = 0; f < 4; f++)
            #pragma unroll
            for (int g = 0; g < 4; g++) {
                const int p = g >> 1, s = g & 1;
                mma16816(acc[f][g], ah[f], bh[p][s], bh[p][s + 2]);
            }
        uint32_t al[4][4];
        #pragma unroll
        for (int f = 0; f < 4; f++)
            ldsm4(al[f], AL + aoff + f * (16 * 80) + ks * 32);
        #pragma unroll
        for (int f = 0; f < 4; f++)
            #pragma unroll
            for (int g = 0; g < 4; g++) {
                const int p = g >> 1, s = g & 1;
                mma16816(acc[f][g], al[f], bh[p][s], bh[p][s + 2]);
            }
    }

    // epilogue (OUTM1: single fp16, bias+relu)
    #pragma unroll
    for (int f = 0; f < 4; f++) {
        const int rg0 = row0 + m_base + f * 16 + (lane >> 2);
        #pragma unroll
        for (int g = 0; g < 4; g++) {
            const int c = n0 + n_base + g * 8 + (lane & 3) * 2;
            const float b0 = bias[c], b1 = bias[c + 1];
            float v00 = fmaxf(acc[f][g][0] + b0, 0.f);
            float v01 = fmaxf(acc[f][g][1] + b1, 0.f);
            float v10 = fmaxf(acc[f][g][2] + b0, 0.f);
            float v11 = fmaxf(acc[f][g][3] + b1, 0.f);
            *(uint32_t*)(Chi + (size_t)rg0 * 512 + c)       = pack_h2(v00, v01);
            *(uint32_t*)(Chi + (size_t)(rg0 + 8) * 512 + c) = pack_h2(v10, v11);
        }
    }
}

// ---------------------------------------------------------------------------
// fp16 mma.sync GEMM (PROVEN config). Block 128x128, warp tile 64x32,
// 2 blocks/SM. NPASS==1 only here. OUTM: 1 = fp16 store;
// 3 = fused final layer: rows<BATCH -> Exk, rows>=BATCH -> zt[.., 32+c],
//     plus zt[:,0:32] = x_next copy for this block's rows.
// ---------------------------------------------------------------------------
template<int KB, int STAGES, bool RELU, int OUTM>
__global__ __launch_bounds__(256, 2)
void gemm_mma(const __half* __restrict__ Ahi, int ldA,
              const __half* __restrict__ Bhi, int ldB,
              const float* __restrict__ bias,
              __half* __restrict__ Chi,
              float* __restrict__ Cf, float* __restrict__ Cf2,
              const float* __restrict__ xnext,
              int ldC, int Nlim)
{
    constexpr int STG = 2 * TILE_B;
    constexpr uint32_t BOFF = TILE_B;

    extern __shared__ __align__(128) uint8_t dsm[];
    const uint32_t sbase = smem_u32(dsm);

    const int tid  = threadIdx.x;
    const int wid  = tid >> 5;
    const int lane = tid & 31;
    const int row0 = blockIdx.y * 128;
    const int n0   = blockIdx.x * 128;

    const int m_base = (wid >> 2) * 64;
    const int n_base = (wid & 3) * 32;

    const uint32_t aoff = (uint32_t)(m_base + (lane & 15)) * 80 + ((lane >> 4) << 4);
    const uint32_t boff = (uint32_t)(n_base + (lane & 15)) * 80 + ((lane >> 4) << 4);

    float acc[4][4][4];
    #pragma unroll
    for (int f = 0; f < 4; f++)
        #pragma unroll
        for (int g = 0; g < 4; g++)
            #pragma unroll
            for (int e = 0; e < 4; e++)
                acc[f][g][e] = 0.f;

    auto load_kb = [&](int kb, int st) {
        const uint32_t sa = sbase + st * STG;
        #pragma unroll
        for (int t = 0; t < 2; t++) {
            int q = tid + t * 256;
            int r = q >> 2, c = q & 3;
            uint32_t so = (uint32_t)r * 80 + c * 16;
            CP16(sa + so, Ahi + (size_t)(row0 + r) * ldA + kb * 32 + c * 8);
            CP16(sa + BOFF + so, Bhi + (size_t)(n0 + r) * ldB + kb * 32 + c * 8);
        }
    };

    auto compute_st = [&](int st) {
        const uint32_t sa = sbase + st * STG;
        #pragma unroll
        for (int ks = 0; ks < 2; ks++) {
            uint32_t ah[4][4], bh[2][4];
            #pragma unroll
            for (int f = 0; f < 4; f++)
                ldsm4(ah[f], sa + aoff + f * (16 * 80) + ks * 32);
            #pragma unroll
            for (int p = 0; p < 2; p++)
                ldsm4(bh[p], sa + BOFF + boff + p * (16 * 80) + ks * 32);
            #pragma unroll
            for (int f = 0; f < 4; f++)
                #pragma unroll
                for (int g = 0; g < 4; g++) {
                    const int p = g >> 1, s = g & 1;
                    mma16816(acc[f][g], ah[f], bh[p][s], bh[p][s + 2]);
                }
        }
    };

    // prologue
    #pragma unroll
    for (int s = 0; s < STAGES - 1; s++) {
        if (s < KB) load_kb(s, s);
        CP_COMMIT();
    }

    // OUTM3: copy x_next rows -> zt[:,0:32] while pipeline fills
    if (OUTM == 3 && row0 >= BATCH) {
        const int rx = row0 - BATCH;
        #pragma unroll
        for (int t = 0; t < 4; t++) {
            int q = tid + t * 256;           // 1024 chunks: 128 rows x 8 float4
            int r = q >> 3, c = q & 7;
            float4 v = *(const float4*)(xnext + (size_t)(rx + r) * 32 + c * 4);
            *(float4*)(Cf2 + (size_t)(rx + r) * LATENT_DIM + c * 4) = v;
        }
    }

    // mainloop
    for (int kb = 0; kb < KB; kb++) {
        CP_WAIT(STAGES - 2);
        __syncthreads();
        const int nkb = kb + STAGES - 1;
        if (nkb < KB) load_kb(nkb, nkb % STAGES);
        CP_COMMIT();
        compute_st(kb % STAGES);
    }

    // epilogue
    #pragma unroll
    for (int f = 0; f < 4; f++) {
        const int rg0 = row0 + m_base + f * 16 + (lane >> 2);
        #pragma unroll
        for (int g = 0; g < 4; g++) {
            const int c = n0 + n_base + g * 8 + (lane & 3) * 2;
            if (c < Nlim) {
                const float b0 = bias[c], b1 = bias[c + 1];
                float v00 = acc[f][g][0] + b0, v01 = acc[f][g][1] + b1;
                float v10 = acc[f][g][2] + b0, v11 = acc[f][g][3] + b1;
                if (RELU) {
                    v00 = fmaxf(v00, 0.f); v01 = fmaxf(v01, 0.f);
                    v10 = fmaxf(v10, 0.f); v11 = fmaxf(v11, 0.f);
                }
                if (OUTM == 1) {
                    *(uint32_t*)(Chi + (size_t)rg0 * ldC + c)       = pack_h2(v00, v01);
                    *(uint32_t*)(Chi + (size_t)(rg0 + 8) * ldC + c) = pack_h2(v10, v11);
                } else {
                    #pragma unroll
                    for (int h = 0; h < 2; h++) {
                        const int rg = rg0 + h * 8;
                        const float va = (h == 0) ? v00 : v10;
                        const float vb = (h == 0) ? v01 : v11;
                        if (rg < BATCH) {
                            Cf[(size_t)rg * EMBED_DIM + c]     = va;
                            Cf[(size_t)rg * EMBED_DIM + c + 1] = vb;
                        } else {
                            float* p = Cf2 + (size_t)(rg - BATCH) * LATENT_DIM
                                     + STATE_DIM + c;
                            p[0] = va; p[1] = vb;
                        }
                    }
                }
            }
        }
    }
}

// ---------------------------------------------------------------------------
// Weights-only converter: W1/W2/W3 (hi), Wo (hi, N padded 96->128), [N][K].
// ---------------------------------------------------------------------------
#define W1C  (512 * 32)
#define W2C  (512 * 512)
#define W3C  (512 * 512)
#define WOC  (128 * 512)
#define CONVTOT (W1C + W2C + W3C + WOC)

__global__ void conv_w(const float* __restrict__ W1, const float* __restrict__ W2,
                       const float* __restrict__ W3, const float* __restrict__ Wo,
                       __half* __restrict__ W1thi,
                       __half* __restrict__ W2thi, __half* __restrict__ W3thi,
                       __half* __restrict__ Wothi)
{
    int i = blockIdx.x * 256 + threadIdx.x;
    if (i < W1C) {
        int k = i / 512, n = i % 512;
        W1thi[n * 32 + k] = __float2half(W1[k * 512 + n]);
        return;
    }
    i -= W1C;
    if (i < W2C) {
        int k = i / 512, n = i % 512;
        W2thi[(size_t)n * 512 + k] = __float2half(W2[(size_t)k * 512 + n]);
        return;
    }
    i -= W2C;
    if (i < W3C) {
        int k = i / 512, n = i % 512;
        W3thi[(size_t)n * 512 + k] = __float2half(W3[(size_t)k * 512 + n]);
        return;
    }
    i -= W3C;
    {
        int k = i / 128, n = i % 128;
        float v = (n < 96) ? Wo[(size_t)k * 96 + n] : 0.f;
        Wothi[(size_t)n * 512 + k] = __float2half(v);
    }
}

// ---------------------------------------------------------------------------
// Scan, row-shared (proven R16): 128 blocks x 128 threads; warp owns 4 rows.
// ---------------------------------------------------------------------------
#define ZPAD 132
#define SC_SMEM ((128 * 128 + 8 * 128 + 16 * ZPAD + 16 * 8) * 4)   // 78592 B

__global__ __launch_bounds__(128, 1)
void scan_kernel(const float* __restrict__ x_k, const float* __restrict__ u_seq,
                 const float* __restrict__ Amat, const float* __restrict__ Bmat,
                 const float* __restrict__ E,
                 float* __restrict__ z_pred, float* __restrict__ x_pred)
{
    extern __shared__ float sm[];
    float* Asm = sm;                         // [128][128]
    float* Bsm = Asm + 128 * 128;            // [8][128]
    float* zsh = Bsm + 8 * 128;              // [16][ZPAD]
    float* ush = zsh + 16 * ZPAD;            // [16][8]

    const int tid  = threadIdx.x;
    const int wid  = tid >> 5;
    const int j    = tid & 31;
    const int rloc = wid * 4 + (j >> 3);
    const int b    = blockIdx.x * 16 + rloc;
    const int cbase = (j & 7) * 4;

    #pragma unroll
    for (int i = 0; i < 32; i++) {
        int idx = tid + i * 128;
        int row = idx >> 5, c4 = idx & 31;
        *(float4*)&Asm[row * 128 + c4 * 4] = ((const float4*)Amat)[idx];
    }
    #pragma unroll
    for (int i = 0; i < 2; i++) {
        int idx = tid + i * 128;
        ((float4*)Bsm)[idx] = ((const float4*)Bmat)[idx];
    }
    {
        float4 v0 = *(const float4*)(x_k + (size_t)b * STATE_DIM + cbase);
        *(float4*)&zsh[rloc * ZPAD + cbase] = v0;
        #pragma unroll
        for (int q = 1; q < 4; q++) {
            float4 v = *(const float4*)(E + (size_t)b * EMBED_DIM + cbase + 32 * q - 32);
            *(float4*)&zsh[rloc * ZPAD + cbase + 32 * q] = v;
        }
    }
    ush[(tid >> 3) * 8 + (tid & 7)] =
        u_seq[((size_t)(blockIdx.x * 16 + (tid >> 3)) * MSEQ + 0) * CONTROL_DIM + (tid & 7)];
    __syncthreads();

    for (int i = 0; i < MSEQ; i++) {
        float2 acc[4][2];
        #pragma unroll
        for (int q = 0; q < 4; q++) {
            acc[q][0] = make_float2(0.f, 0.f);
            acc[q][1] = make_float2(0.f, 0.f);
        }
        #pragma unroll
        for (int c = 0; c < CONTROL_DIM; c++) {
            const float uc = ush[rloc * 8 + c];
            #pragma unroll
            for (int q = 0; q < 4; q++) {
                float4 br = *(float4*)&Bsm[c * 128 + cbase + 32 * q];
                float2 aa = make_float2(uc, uc);
                unsigned long long A0 = *(unsigned long long*)&aa;
                unsigned long long B0, C0;
                float2 t0 = make_float2(br.x, br.y);
                B0 = *(unsigned long long*)&t0; C0 = *(unsigned long long*)&acc[q][0];
                asm("fma.rn.f32x2 %0, %1, %2, %0;" : "+l"(C0) : "l"(A0), "l"(B0));
                acc[q][0] = *(float2*)&C0;
                float2 t1 = make_float2(br.z, br.w);
                B0 = *(unsigned long long*)&t1; C0 = *(unsigned long long*)&acc[q][1];
                asm("fma.rn.f32x2 %0, %1, %2, %0;" : "+l"(C0) : "l"(A0), "l"(B0));
                acc[q][1] = *(float2*)&C0;
            }
        }
        #pragma unroll 4
        for (int k = 0; k < LATENT_DIM; k++) {
            const float zk = zsh[rloc * ZPAD + k];
            float2 aa = make_float2(zk, zk);
            unsigned long long A0 = *(unsigned long long*)&aa;
            #pragma unroll
            for (int q = 0; q < 4; q++) {
                float4 ar = *(float4*)&Asm[k * 128 + cbase + 32 * q];
                unsigned long long B0, C0;
                float2 t0 = make_float2(ar.x, ar.y);
                B0 = *(unsigned long long*)&t0; C0 = *(unsigned long long*)&acc[q][0];
                asm("fma.rn.f32x2 %0, %1, %2, %0;" : "+l"(C0) : "l"(A0), "l"(B0));
                acc[q][0] = *(float2*)&C0;
                float2 t1 = make_float2(ar.z, ar.w);
                B0 = *(unsigned long long*)&t1; C0 = *(unsigned long long*)&acc[q][1];
                asm("fma.rn.f32x2 %0, %1, %2, %0;" : "+l"(C0) : "l"(A0), "l"(B0));
                acc[q][1] = *(float2*)&C0;
            }
        }
        __syncwarp();

        const size_t orow = (size_t)b * MSEQ + i;
        #pragma unroll
        for (int q = 0; q < 4; q++) {
            float4 v = make_float4(acc[q][0].x, acc[q][0].y, acc[q][1].x, acc[q][1].y);
            *(float4*)&zsh[rloc * ZPAD + cbase + 32 * q] = v;
            *(float4*)(z_pred + orow * LATENT_DIM + cbase + 32 * q) = v;
            if (q == 0)
                *(float4*)(x_pred + orow * STATE_DIM + cbase) = v;
        }
        if (i + 1 < MSEQ)
            ush[(tid >> 3) * 8 + (tid & 7)] =
                u_seq[((size_t)(blockIdx.x * 16 + (tid >> 3)) * MSEQ + i + 1) * CONTROL_DIM
                      + (tid & 7)];
        __syncwarp();
    }
}

// ---------------------------------------------------------------------------
// kernel_launch
// Inputs: 0:x_k 1:u_seq 2:x_next_seq 3:W1 4:b1 5:W2 6:b2 7:W3 8:b3
//         9:Wo 10:bo 11:A 12:Bmat
// ---------------------------------------------------------------------------
extern "C" void kernel_launch(void* const* d_in, const int* in_sizes, int n_in,
                              void* d_out, int out_size)
{
    const float* x_k    = (const float*)d_in[0];
    const float* u_seq  = (const float*)d_in[1];
    const float* x_next = (const float*)d_in[2];
    const float* W1     = (const float*)d_in[3];
    const float* b1     = (const float*)d_in[4];
    const float* W2     = (const float*)d_in[5];
    const float* b2     = (const float*)d_in[6];
    const float* W3     = (const float*)d_in[7];
    const float* b3     = (const float*)d_in[8];
    const float* Wo     = (const float*)d_in[9];
    const float* bo     = (const float*)d_in[10];
    const float* Amat   = (const float*)d_in[11];
    const float* Bmat   = (const float*)d_in[12];

    float* out      = (float*)d_out;
    float* z_pred   = out;
    float* x_pred   = out + (size_t)BATCH * MSEQ * LATENT_DIM;
    float* z_target = x_pred + (size_t)BATCH * MSEQ * STATE_DIM;

    __half *Hahi, *Hbhi, *W1thi, *W2thi, *W3thi, *Wothi;
    float* Exk;
    cudaGetSymbolAddress((void**)&Hahi, g_Hahi);
    cudaGetSymbolAddress((void**)&Hbhi, g_Hbhi);
    cudaGetSymbolAddress((void**)&W1thi, g_W1thi);
    cudaGetSymbolAddress((void**)&W2thi, g_W2thi);
    cudaGetSymbolAddress((void**)&W3thi, g_W3thi);
    cudaGetSymbolAddress((void**)&Wothi, g_Wothi);
    cudaGetSymbolAddress((void**)&Exk, g_Exk);

    const int SMEM_P1 = 4 * 2 * TILE_B;   // 81920 (1-pass, 4 stages)
    cudaFuncSetAttribute(gemm_l1,
                         cudaFuncAttributeMaxDynamicSharedMemorySize, L1_SMEM);
    cudaFuncSetAttribute(gemm_mma<16, 4, true,  1>,
                         cudaFuncAttributeMaxDynamicSharedMemorySize, SMEM_P1);
    cudaFuncSetAttribute(gemm_mma<16, 4, false, 3>,
                         cudaFuncAttributeMaxDynamicSharedMemorySize, SMEM_P1);
    cudaFuncSetAttribute(scan_kernel,
                         cudaFuncAttributeMaxDynamicSharedMemorySize, SC_SMEM);

    // weight conversions                                       (launch 1)
    conv_w<<<(CONVTOT + 255) / 256, 256>>>(W1, W2, W3, Wo,
                                           W1thi, W2thi, W3thi, Wothi);

    // L1: fused X-split + 2-pass GEMM -> Hahi                  (launch 2)
    gemm_l1<<<dim3(4, MTILES), 256, L1_SMEM>>>(x_k, x_next, W1thi, b1, Hahi);

    // L2: 1-pass fp16 -> Hbhi                                  (launch 3)
    gemm_mma<16, 4, true, 1><<<dim3(4, MTILES), 256, SMEM_P1>>>(
        Hahi, 512, W2thi, 512, b2, Hbhi, nullptr, nullptr, nullptr, 512, 512);
    // L3: 1-pass fp16 -> Hahi                                  (launch 4)
    gemm_mma<16, 4, true, 1><<<dim3(4, MTILES), 256, SMEM_P1>>>(
        Hbhi, 512, W3thi, 512, b3, Hahi, nullptr, nullptr, nullptr, 512, 512);
    // L4: 1-pass, fused scatter + zt[:,0:32] copy              (launch 5)
    gemm_mma<16, 4, false, 3><<<dim3(1, MTILES), 256, SMEM_P1>>>(
        Hahi, 512, Wothi, 512, bo, nullptr, Exk, z_target, x_next, 96, 96);

    // scan                                                     (launch 6)
    scan_kernel<<<BATCH / 16, 128, SC_SMEM>>>(x_k, u_seq, Amat, Bmat, Exk,
                                              z_pred, x_pred);

    (void)in_sizes; (void)n_in; (void)out_size;
}